// round 4
// baseline (speedup 1.0000x reference)
#include <cuda_runtime.h>

// EMA scan: out[b,t,d] = a*out[b,t-1,d] + (1-a)*x[b,t,d], out[b,-1,d]=0
// Shapes fixed: B=4, S=4096, D=2048, fp32.
//
// Segmented chunked scan, float4 over channels.
// Per segment (1024 timesteps, 33.5MB): pass1 computes per-chunk local EMA
// ends (reads x from DRAM -> populates L2), pass2 chains carries (tiny),
// pass3 re-reads x (L2 hit) and writes outputs (__stcs, evict-first).
// Cross-segment carry flows through g_run, re-initialized at seg 0 each
// replay (graph-deterministic).

#define B 4
#define S 4096
#define D 2048
#define D4 (D / 4)          // 512 float4 lanes
#define SEG_T 1024          // timesteps per segment
#define NSEG (S / SEG_T)    // 4
#define CHUNK 64            // timesteps per chunk
#define CPS (SEG_T / CHUNK) // 16 chunks per segment
#define TPB 128             // threads per CTA (float4 lanes)

constexpr float ALPHA = 0.99f;
constexpr float ONEM  = 0.01f;

constexpr float pow_alpha(int n) {
    double r = 1.0;
    for (int i = 0; i < n; ++i) r *= 0.99;
    return (float)r;
}
constexpr float DEC = pow_alpha(CHUNK);   // alpha^64

__device__ __forceinline__ float4 ema_step(float4 e, float4 v) {
    e.x = fmaf(ALPHA, e.x, ONEM * v.x);
    e.y = fmaf(ALPHA, e.y, ONEM * v.y);
    e.z = fmaf(ALPHA, e.z, ONEM * v.z);
    e.w = fmaf(ALPHA, e.w, ONEM * v.w);
    return e;
}

// Scratch (per-segment lifetime; launches serialize in-stream).
__device__ float4 g_ends [B * CPS * D4];   // chunk-local end EMAs
__device__ float4 g_carry[B * CPS * D4];   // carry (EMA at chunk start)
__device__ float4 g_run  [B * D4];         // running carry across segments

// ---------------------------------------------------------------------------
// Pass 1: per-(b,chunk,d4) local EMA from 0 over CHUNK steps; store end value.
// grid: (D4/TPB, CPS, B) = (4, 16, 4), block: TPB
// ---------------------------------------------------------------------------
__global__ void __launch_bounds__(TPB) ema_pass1(const float4* __restrict__ x4,
                                                 int seg) {
    const int d4 = blockIdx.x * TPB + threadIdx.x;
    const int c = blockIdx.y;
    const int b = blockIdx.z;

    const size_t base =
        ((size_t)b * S + (size_t)seg * SEG_T + (size_t)c * CHUNK) * D4 + d4;

    float4 e = make_float4(0.f, 0.f, 0.f, 0.f);

#pragma unroll 4
    for (int t0 = 0; t0 < CHUNK; t0 += 8) {
        float4 v[8];
#pragma unroll
        for (int j = 0; j < 8; ++j) v[j] = x4[base + (size_t)(t0 + j) * D4];
#pragma unroll
        for (int j = 0; j < 8; ++j) e = ema_step(e, v[j]);
    }

    g_ends[((size_t)b * CPS + c) * D4 + d4] = e;
}

// ---------------------------------------------------------------------------
// Pass 2: chain carries through this segment's chunks; update running carry.
// grid: (B*D4/256), block: 256  (2048 threads, 16 serial steps)
// ---------------------------------------------------------------------------
__global__ void __launch_bounds__(256) ema_pass2(int seg) {
    const int i = blockIdx.x * blockDim.x + threadIdx.x;  // 0..B*D4-1
    const int b = i / D4;
    const int d4 = i % D4;

    float4 E;
    if (seg == 0) E = make_float4(0.f, 0.f, 0.f, 0.f);
    else          E = g_run[i];

#pragma unroll
    for (int c = 0; c < CPS; ++c) {
        const size_t idx = ((size_t)b * CPS + c) * D4 + d4;
        g_carry[idx] = E;
        float4 e = g_ends[idx];
        E.x = fmaf(DEC, E.x, e.x);
        E.y = fmaf(DEC, E.y, e.y);
        E.z = fmaf(DEC, E.z, e.z);
        E.w = fmaf(DEC, E.w, e.w);
    }
    g_run[i] = E;
}

// ---------------------------------------------------------------------------
// Pass 3: exact recurrence seeded with carry; x re-read (L2-hot), out written
// with streaming hint. grid/block identical to pass1.
// ---------------------------------------------------------------------------
__global__ void __launch_bounds__(TPB) ema_pass3(const float4* __restrict__ x4,
                                                 float4* __restrict__ out4,
                                                 int seg) {
    const int d4 = blockIdx.x * TPB + threadIdx.x;
    const int c = blockIdx.y;
    const int b = blockIdx.z;

    const size_t base =
        ((size_t)b * S + (size_t)seg * SEG_T + (size_t)c * CHUNK) * D4 + d4;

    float4 ema = g_carry[((size_t)b * CPS + c) * D4 + d4];

#pragma unroll 4
    for (int t0 = 0; t0 < CHUNK; t0 += 8) {
        float4 v[8];
#pragma unroll
        for (int j = 0; j < 8; ++j) v[j] = x4[base + (size_t)(t0 + j) * D4];
        float4 r[8];
#pragma unroll
        for (int j = 0; j < 8; ++j) {
            ema = ema_step(ema, v[j]);
            r[j] = ema;
        }
#pragma unroll
        for (int j = 0; j < 8; ++j)
            __stcs(&out4[base + (size_t)(t0 + j) * D4], r[j]);
    }
}

extern "C" void kernel_launch(void* const* d_in, const int* in_sizes, int n_in,
                              void* d_out, int out_size) {
    const float4* x4 = (const float4*)d_in[0];
    float4* out4 = (float4*)d_out;

    dim3 g1(D4 / TPB, CPS, B);            // (4, 16, 4) = 256 CTAs
    for (int seg = 0; seg < NSEG; ++seg) {
        ema_pass1<<<g1, TPB>>>(x4, seg);
        ema_pass2<<<(B * D4) / 256, 256>>>(seg);
        ema_pass3<<<g1, TPB>>>(x4, out4, seg);
    }
}

// round 5
// speedup vs baseline: 1.9664x; 1.9664x over previous
#include <cuda_runtime.h>

// EMA scan: out[b,t,d] = a*out[b,t-1,d] + (1-a)*x[b,t,d], out[b,-1,d]=0
// Shapes fixed: B=4, S=4096, D=2048, fp32.
//
// Chunked 3-pass scan, float4 lanes, 2 L2-sized segments.
// Occupancy is the binding constraint on this chip (rounds 2-4 evidence):
// per-pass grids are 1024 CTAs x 128 threads = 4096 warps (~28/SM).

#define B 4
#define S 4096
#define D 2048
#define D4 (D / 4)            // 512 float4 lanes
#define SEG_T 2048            // timesteps per segment (67MB < 126MB L2)
#define NSEG (S / SEG_T)      // 2
#define CHUNK 32              // timesteps per chunk
#define CPS (SEG_T / CHUNK)   // 64 chunks per segment
#define TPB 128

constexpr float ALPHA = 0.99f;
constexpr float ONEM  = 0.01f;

constexpr float pow_alpha(int n) {
    double r = 1.0;
    for (int i = 0; i < n; ++i) r *= 0.99;
    return (float)r;
}
constexpr float DEC = pow_alpha(CHUNK);   // alpha^32

__device__ __forceinline__ float4 ema_step(float4 e, float4 v) {
    e.x = fmaf(ALPHA, e.x, ONEM * v.x);
    e.y = fmaf(ALPHA, e.y, ONEM * v.y);
    e.z = fmaf(ALPHA, e.z, ONEM * v.z);
    e.w = fmaf(ALPHA, e.w, ONEM * v.w);
    return e;
}

// Scratch (per-segment lifetime; stream-serialized launches).
__device__ float4 g_ends [B * CPS * D4];   // chunk-local end EMAs
__device__ float4 g_carry[B * CPS * D4];   // carry (global EMA at chunk start)
__device__ float4 g_run  [B * D4];         // running carry across segments

// ---------------------------------------------------------------------------
// Pass 1: local EMA from 0 over CHUNK steps; store chunk-end value.
// grid: (D4/TPB, CPS, B) = (4, 64, 4) = 1024 CTAs
// ---------------------------------------------------------------------------
__global__ void __launch_bounds__(TPB) ema_pass1(const float4* __restrict__ x4,
                                                 int seg) {
    const int d4 = blockIdx.x * TPB + threadIdx.x;
    const int c = blockIdx.y;
    const int b = blockIdx.z;

    const size_t base =
        ((size_t)b * S + (size_t)seg * SEG_T + (size_t)c * CHUNK) * D4 + d4;

    float4 e = make_float4(0.f, 0.f, 0.f, 0.f);

#pragma unroll 4
    for (int t0 = 0; t0 < CHUNK; t0 += 8) {
        float4 v[8];
#pragma unroll
        for (int j = 0; j < 8; ++j) v[j] = x4[base + (size_t)(t0 + j) * D4];
#pragma unroll
        for (int j = 0; j < 8; ++j) e = ema_step(e, v[j]);
    }

    g_ends[((size_t)b * CPS + c) * D4 + d4] = e;
}

// ---------------------------------------------------------------------------
// Pass 2: chain carries through this segment's chunks (scalar lanes; 8192
// threads, 64 serial steps, batched prefetch). Updates g_run.
// ---------------------------------------------------------------------------
__global__ void __launch_bounds__(256) ema_pass2(int seg) {
    const int i = blockIdx.x * blockDim.x + threadIdx.x;  // 0..B*D-1
    const int b = i / D;
    const int dd = i % D;       // scalar float index into the float4 arrays

    const float* ends = (const float*)g_ends;
    float* carry = (float*)g_carry;
    float* run = (float*)g_run;

    float E = (seg == 0) ? 0.0f : run[i];

#pragma unroll
    for (int c0 = 0; c0 < CPS; c0 += 8) {
        float e[8];
#pragma unroll
        for (int j = 0; j < 8; ++j)
            e[j] = ends[((size_t)b * CPS + c0 + j) * D + dd];
#pragma unroll
        for (int j = 0; j < 8; ++j) {
            carry[((size_t)b * CPS + c0 + j) * D + dd] = E;
            E = fmaf(DEC, E, e[j]);
        }
    }
    run[i] = E;
}

// ---------------------------------------------------------------------------
// Pass 3: exact recurrence seeded with carry; x re-read (L2-hot), outputs
// written evict-first. grid identical to pass1.
// ---------------------------------------------------------------------------
__global__ void __launch_bounds__(TPB) ema_pass3(const float4* __restrict__ x4,
                                                 float4* __restrict__ out4,
                                                 int seg) {
    const int d4 = blockIdx.x * TPB + threadIdx.x;
    const int c = blockIdx.y;
    const int b = blockIdx.z;

    const size_t base =
        ((size_t)b * S + (size_t)seg * SEG_T + (size_t)c * CHUNK) * D4 + d4;

    float4 ema = g_carry[((size_t)b * CPS + c) * D4 + d4];

#pragma unroll 4
    for (int t0 = 0; t0 < CHUNK; t0 += 8) {
        float4 v[8];
#pragma unroll
        for (int j = 0; j < 8; ++j) v[j] = x4[base + (size_t)(t0 + j) * D4];
        float4 r[8];
#pragma unroll
        for (int j = 0; j < 8; ++j) {
            ema = ema_step(ema, v[j]);
            r[j] = ema;
        }
#pragma unroll
        for (int j = 0; j < 8; ++j)
            __stcs(&out4[base + (size_t)(t0 + j) * D4], r[j]);
    }
}

extern "C" void kernel_launch(void* const* d_in, const int* in_sizes, int n_in,
                              void* d_out, int out_size) {
    const float4* x4 = (const float4*)d_in[0];
    float4* out4 = (float4*)d_out;

    dim3 g1(D4 / TPB, CPS, B);            // (4, 64, 4) = 1024 CTAs
    for (int seg = 0; seg < NSEG; ++seg) {
        ema_pass1<<<g1, TPB>>>(x4, seg);
        ema_pass2<<<(B * D) / 256, 256>>>(seg);
        ema_pass3<<<g1, TPB>>>(x4, out4, seg);
    }
}